// round 6
// baseline (speedup 1.0000x reference)
#include <cuda_runtime.h>

// ZNCC fused, warp-per-channel, vertical-first sliding windows.
// CTA = 96 threads = 3 warps; warp w handles channel w of one
// (batch, strip, col-group) tile: 64 raw cols (2/lane) x 32 output rows.
// Stage 1: vertical 5-sum rings on raw x,y (ring also provides t-2 center).
// Stage 2: horizontal 5-sums via shuffles -> means -> centered products ->
//          horizontal product sums -> vertical q rings -> NCC.
// Per-channel rows land in an smem plane; one __syncthreads; fixed-order
// combine (deterministic) and coalesced store.

#define HH 512
#define WW 512
#define CHAN 3
#define SSTRIP 32
#define NSTRIPS (HH / SSTRIP)          // 16
#define OUTCOLS 56
#define NGROUPS 10                     // 10*56 = 560 >= 512
#define NBATCH 16
#define NCTAS (NGROUPS * NSTRIPS * NBATCH)   // 2560
#define PSTRIDE 58                     // plane row stride (even -> float2 STS)

__global__ __launch_bounds__(96, 9)
void zncc_warp_kernel(const float* __restrict__ xg,
                      const float* __restrict__ yg,
                      float* __restrict__ outg)
{
    __shared__ float plane[CHAN][SSTRIP][PSTRIDE];

    const unsigned FULL = 0xFFFFFFFFu;
    const int tid  = threadIdx.x;
    const int lane = tid & 31;
    const int ch   = tid >> 5;          // warp id == channel

    const int task  = blockIdx.x;
    const int b     = task / (NGROUPS * NSTRIPS);
    const int rem   = task - b * (NGROUPS * NSTRIPS);
    const int strip = rem / NGROUPS;
    const int g     = rem - strip * NGROUPS;

    const int r0  = strip * SSTRIP;
    const int gcA = g * OUTCOLS - 4 + 2 * lane;   // even
    const int gcB = gcA + 1;
    const float mA = (gcA >= 0 && gcA < WW) ? 1.0f : 0.0f;
    const float mB = (gcB >= 0 && gcB < WW) ? 1.0f : 0.0f;
    const bool outLane = (lane >= 2) && (lane <= 29) && (gcA < WW);
    const int gca_c = min(max(gcA, 0), WW - 2);   // clamped, float2-safe
    const int pcol  = 2 * lane - 4;               // plane column for col A

    const float inv25 = 1.0f / 25.0f;
    const float inv3  = 1.0f / 3.0f;

    const float* xb = xg + (size_t)(b * CHAN + ch) * (HH * WW);
    const float* yb = yg + (size_t)(b * CHAN + ch) * (HH * WW);

    // raw rings (rows t-4..t per col) and product-rowsum rings
    float rxA[5], rxB[5], ryA[5], ryB[5];
    float qxyA[5], qxyB[5], qxxA[5], qxxB[5], qyyA[5], qyyB[5];
    #pragma unroll
    for (int i = 0; i < 5; i++) {
        rxA[i] = rxB[i] = ryA[i] = ryB[i] = 0.f;
        qxyA[i] = qxyB[i] = qxxA[i] = qxxB[i] = qyyA[i] = qyyB[i] = 0.f;
    }
    float sVxA = 0.f, sVxB = 0.f, sVyA = 0.f, sVyB = 0.f;       // vertical raw sums
    float sQxyA = 0.f, sQxyB = 0.f, sQxxA = 0.f, sQxxB = 0.f, sQyyA = 0.f, sQyyB = 0.f;

    // streaming pointers (row t+1 position after initial prefetch)
    const float* xp = xb + (ptrdiff_t)(r0 - 4) * WW + gca_c;
    const float* yp = yb + (ptrdiff_t)(r0 - 4) * WW + gca_c;

    // staged next-row values (software prefetch): row r0-4
    float2 nvx = make_float2(0.f, 0.f), nvy = make_float2(0.f, 0.f);
    if (r0 - 4 >= 0) {
        nvx = *(const float2*)xp;
        nvy = *(const float2*)yp;
    }
    xp += WW; yp += WW;
    int tn = r0 - 3;                    // next row to prefetch

    for (int sb = 0; sb < SSTRIP + 8; sb += 5) {
        #pragma unroll
        for (int k = 0; k < 5; k++) {
            const int s = sb + k;                 // s % 5 == k
            const int t = r0 - 4 + s;             // raw row consumed now

            // ---- consume staged row t, issue loads for row t+1 ----
            float vxA = nvx.x * mA, vxB = nvx.y * mB;
            float vyA = nvy.x * mA, vyB = nvy.y * mB;
            if (tn >= 0 && tn < HH) {             // warp-uniform
                nvx = *(const float2*)xp;
                nvy = *(const float2*)yp;
            } else {
                nvx = make_float2(0.f, 0.f);
                nvy = make_float2(0.f, 0.f);
            }
            xp += WW; yp += WW; tn++;
            if (t < 0) { vxA = vxB = vyA = vyB = 0.f; }

            // ---- vertical sliding sums of raw; ring holds rows t-4..t ----
            sVxA += vxA - rxA[k]; rxA[k] = vxA;
            sVxB += vxB - rxB[k]; rxB[k] = vxB;
            sVyA += vyA - ryA[k]; ryA[k] = vyA;
            sVyB += vyB - ryB[k]; ryB[k] = vyB;

            if (s >= 4) {
                const int tm = t - 2;             // center row of the window
                const float rm = (tm >= 0 && tm < HH) ? 1.0f : 0.0f;

                // ---- horizontal 5-sums of vertical sums via shuffles ----
                float SxAm = __shfl_up_sync(FULL, sVxA, 1);
                float SxBm = __shfl_up_sync(FULL, sVxB, 1);
                float SxAp = __shfl_down_sync(FULL, sVxA, 1);
                float SxBp = __shfl_down_sync(FULL, sVxB, 1);
                float cx   = SxBm + sVxA + sVxB + SxAp;
                float SxE  = cx + SxAm;           // 5x5 raw sum, col A
                float SxO  = cx + SxBp;           // col B

                float SyAm = __shfl_up_sync(FULL, sVyA, 1);
                float SyBm = __shfl_up_sync(FULL, sVyB, 1);
                float SyAp = __shfl_down_sync(FULL, sVyA, 1);
                float SyBp = __shfl_down_sync(FULL, sVyB, 1);
                float cy   = SyBm + sVyA + sVyB + SyAp;
                float SyE  = cy + SyAm;
                float SyO  = cy + SyBp;

                // centered values at row tm; raw center from ring (row t-2)
                const float fmA = mA * rm, fmB = mB * rm;
                float xcA = fmaf(SxE, -inv25, rxA[(k + 3) % 5]) * fmA;
                float xcB = fmaf(SxO, -inv25, rxB[(k + 3) % 5]) * fmB;
                float ycA = fmaf(SyE, -inv25, ryA[(k + 3) % 5]) * fmA;
                float ycB = fmaf(SyO, -inv25, ryB[(k + 3) % 5]) * fmB;

                // neighbors of xc,yc
                float xcAm = __shfl_up_sync(FULL, xcA, 1);
                float xcBm = __shfl_up_sync(FULL, xcB, 1);
                float xcAp = __shfl_down_sync(FULL, xcA, 1);
                float xcBp = __shfl_down_sync(FULL, xcB, 1);
                float ycAm = __shfl_up_sync(FULL, ycA, 1);
                float ycBm = __shfl_up_sync(FULL, ycB, 1);
                float ycAp = __shfl_down_sync(FULL, ycA, 1);
                float ycBp = __shfl_down_sync(FULL, ycB, 1);

                // horizontal 5-sums of products (shared middle-4 term)
                float c4xy = xcBm * ycBm + xcA * ycA + xcB * ycB + xcAp * ycAp;
                float qxyE = c4xy + xcAm * ycAm;
                float qxyO = c4xy + xcBp * ycBp;
                float c4xx = xcBm * xcBm + xcA * xcA + xcB * xcB + xcAp * xcAp;
                float qxxE = c4xx + xcAm * xcAm;
                float qxxO = c4xx + xcBp * xcBp;
                float c4yy = ycBm * ycBm + ycA * ycA + ycB * ycB + ycAp * ycAp;
                float qyyE = c4yy + ycAm * ycAm;
                float qyyO = c4yy + ycBp * ycBp;

                // vertical sliding sums of q
                sQxyA += qxyE - qxyA[k]; qxyA[k] = qxyE;
                sQxyB += qxyO - qxyB[k]; qxyB[k] = qxyO;
                sQxxA += qxxE - qxxA[k]; qxxA[k] = qxxE;
                sQxxB += qxxO - qxxB[k]; qxxB[k] = qxxO;
                sQyyA += qyyE - qyyA[k]; qyyA[k] = qyyE;
                sQyyB += qyyO - qyyB[k]; qyyB[k] = qyyO;

                if (s >= 8) {
                    const int row = s - 8;        // output row within strip
                    float dA = sqrtf(fmaxf(sQxxA * sQyyA, 0.f)) + 2.5e-7f;
                    float dB = sqrtf(fmaxf(sQxxB * sQyyB, 0.f)) + 2.5e-7f;
                    float nA = __fdividef(sQxyA, dA);
                    float nB = __fdividef(sQxyB, dB);
                    if (outLane) {
                        *(float2*)&plane[ch][row][pcol] = make_float2(nA, nB);
                    }
                }
            }
        }
    }

    __syncthreads();

    // ---- combine channels in fixed order (deterministic) and write out ----
    float* outp = outg + (size_t)b * (HH * WW) + (size_t)r0 * WW + g * OUTCOLS;
    for (int idx = tid; idx < SSTRIP * OUTCOLS; idx += 96) {
        int row = idx / OUTCOLS;
        int c   = idx - row * OUTCOLS;
        if (g * OUTCOLS + c < WW) {
            float v = (plane[0][row][c] + plane[1][row][c] + plane[2][row][c]) * inv3;
            outp[(size_t)row * WW + c] = v;
        }
    }
}

extern "C" void kernel_launch(void* const* d_in, const int* in_sizes, int n_in,
                              void* d_out, int out_size)
{
    const float* x = (const float*)d_in[0];
    const float* y = (const float*)d_in[1];
    float* out = (float*)d_out;

    zncc_warp_kernel<<<NCTAS, 96>>>(x, y, out);
}